// round 12
// baseline (speedup 1.0000x reference)
#include <cuda_runtime.h>

#define T_LEN 512
#define B_SZ  512
#define I_SZ  100
#define H_SZ  96
#define G3    288   // 3*H
#define BCH   7     // batch rows per scan block (74 chunks x 2 dirs = 148 blocks)
#define NCHUNK 74
#define PROJ_T 384   // 48 jj x 8 k-eighths
#define SCAN_T 384   // 96 j  x 4 k-quarters
#define HPAD  100    // padded h row (bank-conflict-free duty stores)

typedef unsigned long long u64;

// Scratch: input projections for both directions: [2][T][B][3H] fp32
static __device__ float g_xproj[2ull * T_LEN * B_SZ * G3];

// ---- packed fp32x2 helpers (sm_103a FFMA2 path; bit-identical to 2x fmaf) ----
__device__ __forceinline__ u64 ffma2(u64 a, u64 b, u64 c) {
    u64 d;
    asm("fma.rn.f32x2 %0, %1, %2, %3;" : "=l"(d) : "l"(a), "l"(b), "l"(c));
    return d;
}
__device__ __forceinline__ u64 pack2(float lo, float hi) {
    u64 p;
    asm("mov.b64 %0, {%1, %2};" : "=l"(p) : "f"(lo), "f"(hi));
    return p;
}
__device__ __forceinline__ float hsum2(u64 p) {
    float lo, hi;
    asm("mov.b64 {%0, %1}, %2;" : "=f"(lo), "=f"(hi) : "l"(p));
    return lo + hi;
}
// combine the 4 k-quarter partials held by lanes l, l^8, l^16, l^24 (scan)
__device__ __forceinline__ float qreduce(float v) {
    v += __shfl_xor_sync(0xffffffffu, v, 8);
    v += __shfl_xor_sync(0xffffffffu, v, 16);
    return v;
}
// combine the 8 k-eighth partials held by lanes differing in bits 0-2 (proj)
__device__ __forceinline__ float qreduce8(float v) {
    v += __shfl_xor_sync(0xffffffffu, v, 4);
    v += __shfl_xor_sync(0xffffffffu, v, 2);
    v += __shfl_xor_sync(0xffffffffu, v, 1);
    return v;
}

__device__ __forceinline__ float fast_sigmoid(float x) {
    float e, r;
    asm("ex2.approx.f32 %0, %1;" : "=f"(e) : "f"(-1.4426950408889634f * x));
    asm("rcp.approx.f32 %0, %1;" : "=f"(r) : "f"(1.0f + e));
    return r;
}
__device__ __forceinline__ float fast_tanh(float x) {
    float e, r;
    asm("ex2.approx.f32 %0, %1;" : "=f"(e) : "f"(-2.8853900817779268f * x));
    asm("rcp.approx.f32 %0, %1;" : "=f"(r) : "f"(1.0f + e));
    return 2.0f * r - 1.0f;
}

// ---------------------------------------------------------------------------
// Projection v5 (barrier-free, 6 gate-rows/thread, 8-way split-k):
// 384 threads: lane = jjl*8 + q; jj = warp*4 + jjl in [0,48), q = k-eighth.
// Thread owns gate rows jj + 48r, r = 0..5.
// k window per q: floats [12q, 12q+16) (16B-aligned; q<7 zero-pads the last
// 4 weights so the overlap with the next window contributes 0; q=7 covers
// [84,100) exactly). 4 LDG.128 feed 48 FFMA2 -> 12 FMA2 per load.
// qreduce8 combines eighths; lane q==r stores row jj+48q. No __syncthreads.
// ---------------------------------------------------------------------------
__global__ __launch_bounds__(PROJ_T, 1) void proj_kernel(
    const float* __restrict__ x,
    const float* __restrict__ w_ih_f, const float* __restrict__ b_ih_f,
    const float* __restrict__ w_ih_b, const float* __restrict__ b_ih_b)
{
    const int dir    = blockIdx.x & 1;
    const int chunk  = blockIdx.x >> 1;
    const int nchunk = gridDim.x >> 1;
    const long R = (long)T_LEN * B_SZ;
    const long rows_per = (R + nchunk - 1) / nchunk;
    const long r0 = (long)chunk * rows_per;
    const long r1 = (r0 + rows_per < R) ? (r0 + rows_per) : R;

    const float* w    = dir ? w_ih_b : w_ih_f;
    const float* bias = dir ? b_ih_b : b_ih_f;
    float* xp = g_xproj + (size_t)dir * T_LEN * B_SZ * G3;

    const int t    = threadIdx.x;
    const int lane = t & 31;
    const int q    = lane & 7;                  // k-eighth
    const int jj   = (t >> 5) * 4 + (lane >> 3);// 0..47

    // weights: 6 rows x 8 u64 (floats [12q,12q+16) of each row, zero-padded)
    u64 wr[6][8];
    #pragma unroll
    for (int r = 0; r < 6; r++) {
        const ulonglong2* p =
            (const ulonglong2*)(w + (jj + 48 * r) * I_SZ + 12 * q);
        ulonglong2 c0 = p[0], c1 = p[1], c2 = p[2], c3 = p[3];
        wr[r][0] = c0.x; wr[r][1] = c0.y;
        wr[r][2] = c1.x; wr[r][3] = c1.y;
        wr[r][4] = c2.x; wr[r][5] = c2.y;
        wr[r][6] = (q == 7) ? c3.x : 0ull;
        wr[r][7] = (q == 7) ? c3.y : 0ull;
    }
    float bg[6];
    #pragma unroll
    for (int r = 0; r < 6; r++) bg[r] = q ? 0.0f : bias[jj + 48 * r];

    // 2-deep pipeline: xv holds row 'row', loads for row+1 issue before reduce
    ulonglong2 xv[4];
    {
        const ulonglong2* xa = (const ulonglong2*)(x + r0 * I_SZ + 12 * q);
        #pragma unroll
        for (int c = 0; c < 4; c++) xv[c] = xa[c];
    }

    #pragma unroll 2
    for (long row = r0; row < r1; ++row) {
        // prefetch next row's window (clamped: stays in-bounds, value unused on tail)
        const long nrow = (row + 1 < r1) ? row + 1 : row;
        const ulonglong2* xa = (const ulonglong2*)(x + nrow * I_SZ + 12 * q);
        ulonglong2 xn0 = xa[0], xn1 = xa[1], xn2 = xa[2], xn3 = xa[3];

        u64 acc[6];
        #pragma unroll
        for (int r = 0; r < 6; r++) acc[r] = pack2(bg[r], 0.0f);
        #pragma unroll
        for (int c = 0; c < 4; c++) {
            #pragma unroll
            for (int r = 0; r < 6; r++) {
                acc[r] = ffma2(xv[c].x, wr[r][2 * c],     acc[r]);
                acc[r] = ffma2(xv[c].y, wr[r][2 * c + 1], acc[r]);
            }
        }

        // combine the 8 k-eighths; all lanes get the 6 full sums
        float s0 = qreduce8(hsum2(acc[0]));
        float s1 = qreduce8(hsum2(acc[1]));
        float s2 = qreduce8(hsum2(acc[2]));
        float s3 = qreduce8(hsum2(acc[3]));
        float s4 = qreduce8(hsum2(acc[4]));
        float s5 = qreduce8(hsum2(acc[5]));

        // duty: lane q stores gate row jj + 48q (q = 0..5; 6,7 idle)
        float myv = s0;
        myv = (q == 1) ? s1 : myv;
        myv = (q == 2) ? s2 : myv;
        myv = (q == 3) ? s3 : myv;
        myv = (q == 4) ? s4 : myv;
        myv = (q == 5) ? s5 : myv;
        if (q < 6) xp[row * G3 + jj + 48 * q] = myv;

        xv[0] = xn0; xv[1] = xn1; xv[2] = xn2; xv[3] = xn3;
    }
}

// ---------------------------------------------------------------------------
// Scan (R10 winner, unchanged): 384 threads, thread = (j, q), owns gate rows
// j, j+96, j+192; duty lanes compute gates in registers; h double-buffered
// in smem; ONE __syncthreads per step.
// ---------------------------------------------------------------------------
__global__ __launch_bounds__(SCAN_T, 1) void scan_kernel(
    const float* __restrict__ w_hh_f, const float* __restrict__ b_hh_f,
    const float* __restrict__ w_hh_b, const float* __restrict__ b_hh_b,
    float* __restrict__ out)
{
    const int dir = blockIdx.y;
    const int b0  = blockIdx.x * BCH;
    const float* w    = dir ? w_hh_b : w_hh_f;
    const float* bias = dir ? b_hh_b : b_hh_f;
    const float* xp = g_xproj + (size_t)dir * T_LEN * B_SZ * G3;

    const int t    = threadIdx.x;
    const int lane = t & 31;
    const int q    = lane >> 3;
    const int j    = (t >> 5) * 8 + (lane & 7);   // 0..95

    // weights: rows j, j+96, j+192; k in [24q, 24q+24): 12 u64 each
    u64 wr[3][12];
    #pragma unroll
    for (int r = 0; r < 3; r++) {
        const u64* p = (const u64*)(w + (j + 96 * r) * H_SZ + 24 * q);
        #pragma unroll
        for (int k = 0; k < 12; k++) wr[r][k] = p[k];
    }
    float bg[3];
    #pragma unroll
    for (int r = 0; r < 3; r++) bg[r] = q ? 0.0f : bias[j + 96 * r];

    // double-buffered hidden state, rows padded to HPAD floats
    __shared__ __align__(16) float h_s[2][BCH][HPAD];
    for (int idx = t; idx < 2 * BCH * HPAD; idx += SCAN_T) ((float*)h_s)[idx] = 0.0f;

    // duty batches for this lane: b = q and q+4
    const int bd0 = q;
    const int bd1 = q + 4;               // valid iff < BCH
    const bool d1v = (bd1 < BCH);
    int row0 = b0 + bd0; if (row0 > B_SZ - 1) row0 = B_SZ - 1;
    int row1 = b0 + (d1v ? bd1 : 0); if (row1 > B_SZ - 1) row1 = B_SZ - 1;
    const bool w0v = (b0 + bd0 < B_SZ);
    const bool w1v = d1v && (b0 + bd1 < B_SZ);

    float hold0 = 0.0f, hold1 = 0.0f;    // this lane's h[b][j], prev step

    // prime xq for step 0 (duty lanes)
    float xq0[3], xq1[3];
    {
        const int t0 = dir ? (T_LEN - 1) : 0;
        const float* p0 = xp + ((size_t)t0 * B_SZ + row0) * G3 + j;
        const float* p1 = xp + ((size_t)t0 * B_SZ + row1) * G3 + j;
        #pragma unroll
        for (int r = 0; r < 3; r++) {
            xq0[r] = p0[96 * r];
            xq1[r] = d1v ? p1[96 * r] : 0.0f;
        }
    }
    __syncthreads();

    int p = 0;
    for (int it = 0; it < T_LEN; it++) {
        const int tc = dir ? (T_LEN - 1 - it) : it;

        // prefetch next step's xq (DRAM latency hidden under this step)
        float xn0[3], xn1[3];
        #pragma unroll
        for (int r = 0; r < 3; r++) { xn0[r] = 0.0f; xn1[r] = 0.0f; }
        if (it + 1 < T_LEN) {
            const int tn = dir ? (T_LEN - 2 - it) : (it + 1);
            const float* p0 = xp + ((size_t)tn * B_SZ + row0) * G3 + j;
            const float* p1 = xp + ((size_t)tn * B_SZ + row1) * G3 + j;
            #pragma unroll
            for (int r = 0; r < 3; r++) {
                xn0[r] = p0[96 * r];
                xn1[r] = d1v ? p1[96 * r] : 0.0f;
            }
        }

        // partial hp for 3 rows x BCH batches, this thread's k-quarter
        u64 acc[3][BCH];
        #pragma unroll
        for (int r = 0; r < 3; r++)
            #pragma unroll
            for (int b = 0; b < BCH; b++) acc[r][b] = pack2(bg[r], 0.0f);

        const ulonglong2* h2 = (const ulonglong2*)h_s[p] + q * 6;  // row = 25 u2
        #pragma unroll
        for (int kk = 0; kk < 6; kk++) {
            #pragma unroll
            for (int b = 0; b < BCH; b++) {
                ulonglong2 hv = h2[b * (HPAD / 4) + kk];
                #pragma unroll
                for (int r = 0; r < 3; r++) {
                    acc[r][b] = ffma2(hv.x, wr[r][2 * kk],     acc[r][b]);
                    acc[r][b] = ffma2(hv.y, wr[r][2 * kk + 1], acc[r][b]);
                }
            }
        }

        // reduce quartets; keep only this lane's duty batches (less reg pressure)
        float v0d[3], v1d[3];
        #pragma unroll
        for (int r = 0; r < 3; r++) {
            #pragma unroll
            for (int b = 0; b < BCH; b++) {
                const float vv = qreduce(hsum2(acc[r][b]));
                if (b == bd0) v0d[r] = vv;
                if (d1v && b == bd1) v1d[r] = vv;
            }
        }

        // duty lane computes gates fully in registers, writes new h
        {
            const float rg = fast_sigmoid(v0d[0] + xq0[0]);
            const float zg = fast_sigmoid(v0d[1] + xq0[1]);
            const float ng = fast_tanh(fmaf(rg, v0d[2], xq0[2]));
            const float hn = fmaf(zg, hold0 - ng, ng);
            hold0 = hn;
            h_s[p ^ 1][bd0][j] = hn;
            if (w0v)
                out[((size_t)tc * B_SZ + (b0 + bd0)) * (2 * H_SZ) + dir * H_SZ + j] = hn;
        }
        if (d1v) {
            const float rg = fast_sigmoid(v1d[0] + xq1[0]);
            const float zg = fast_sigmoid(v1d[1] + xq1[1]);
            const float ng = fast_tanh(fmaf(rg, v1d[2], xq1[2]));
            const float hn = fmaf(zg, hold1 - ng, ng);
            hold1 = hn;
            h_s[p ^ 1][bd1][j] = hn;
            if (w1v)
                out[((size_t)tc * B_SZ + (b0 + bd1)) * (2 * H_SZ) + dir * H_SZ + j] = hn;
        }

        #pragma unroll
        for (int r = 0; r < 3; r++) { xq0[r] = xn0[r]; xq1[r] = xn1[r]; }

        __syncthreads();
        p ^= 1;
    }
}

extern "C" void kernel_launch(void* const* d_in, const int* in_sizes, int n_in,
                              void* d_out, int out_size) {
    const float* x    = (const float*)d_in[0];
    const float* wihf = (const float*)d_in[1];
    const float* whhf = (const float*)d_in[2];
    const float* bihf = (const float*)d_in[3];
    const float* bhhf = (const float*)d_in[4];
    const float* wihb = (const float*)d_in[5];
    const float* whhb = (const float*)d_in[6];
    const float* bihb = (const float*)d_in[7];
    const float* bhhb = (const float*)d_in[8];
    float* out = (float*)d_out;

    proj_kernel<<<148, PROJ_T>>>(x, wihf, bihf, wihb, bihb);
    dim3 sg(NCHUNK, 2);
    scan_kernel<<<sg, SCAN_T>>>(whhf, bhhf, whhb, bhhb, out);
}

// round 13
// speedup vs baseline: 1.8666x; 1.8666x over previous
#include <cuda_runtime.h>
#include <cuda_bf16.h>

#define T_LEN 512
#define B_SZ  512
#define I_SZ  100
#define H_SZ  96
#define G3    288   // 3*H
#define BCH   7     // batch rows per scan block (74 chunks x 2 dirs = 148 blocks)
#define NCHUNK 74
#define PROJ_T 576   // 18 warps = 18 m16 gate-slices
#define SCAN_T 384   // 96 j x 4 k-quarters
#define HPAD  100    // padded h row (bank-conflict-free duty stores)
#define XROW  120    // smem x row stride in bf16 halves (bank-conflict-free)

typedef unsigned int u32;
typedef unsigned long long u64;

// Scratch: input projections for both directions: [2][T][B][3H] fp32
static __device__ float g_xproj[2ull * T_LEN * B_SZ * G3];

// ---- packed fp32x2 helpers (sm_103a FFMA2 path) ----
__device__ __forceinline__ u64 ffma2(u64 a, u64 b, u64 c) {
    u64 d;
    asm("fma.rn.f32x2 %0, %1, %2, %3;" : "=l"(d) : "l"(a), "l"(b), "l"(c));
    return d;
}
__device__ __forceinline__ u64 pack2(float lo, float hi) {
    u64 p;
    asm("mov.b64 %0, {%1, %2};" : "=l"(p) : "f"(lo), "f"(hi));
    return p;
}
__device__ __forceinline__ float hsum2(u64 p) {
    float lo, hi;
    asm("mov.b64 {%0, %1}, %2;" : "=f"(lo), "=f"(hi) : "l"(p));
    return lo + hi;
}
__device__ __forceinline__ float qreduce(float v) {
    v += __shfl_xor_sync(0xffffffffu, v, 8);
    v += __shfl_xor_sync(0xffffffffu, v, 16);
    return v;
}

__device__ __forceinline__ float fast_sigmoid(float x) {
    float e, r;
    asm("ex2.approx.f32 %0, %1;" : "=f"(e) : "f"(-1.4426950408889634f * x));
    asm("rcp.approx.f32 %0, %1;" : "=f"(r) : "f"(1.0f + e));
    return r;
}
__device__ __forceinline__ float fast_tanh(float x) {
    float e, r;
    asm("ex2.approx.f32 %0, %1;" : "=f"(e) : "f"(-2.8853900817779268f * x));
    asm("rcp.approx.f32 %0, %1;" : "=f"(r) : "f"(1.0f + e));
    return 2.0f * r - 1.0f;
}

// ---- bf16 helpers ----
__device__ __forceinline__ u32 bfpack(float a, float b) {
    // low 16 bits = a (even k), high = b (odd k)
    unsigned short sa = __bfloat16_as_ushort(__float2bfloat16(a));
    unsigned short sb = __bfloat16_as_ushort(__float2bfloat16(b));
    return (u32)sa | ((u32)sb << 16);
}
__device__ __forceinline__ void bfsplit(float v, float& hi, float& lo) {
    __nv_bfloat16 h = __float2bfloat16(v);
    hi = __bfloat162float(h);
    lo = v - hi;
}

__device__ __forceinline__ void mma_bf16(
    float& c0, float& c1, float& c2, float& c3,
    u32 a0, u32 a1, u32 a2, u32 a3, u32 b0, u32 b1)
{
    asm("mma.sync.aligned.m16n8k16.row.col.f32.bf16.bf16.f32 "
        "{%0,%1,%2,%3}, {%4,%5,%6,%7}, {%8,%9}, {%0,%1,%2,%3};"
        : "+f"(c0), "+f"(c1), "+f"(c2), "+f"(c3)
        : "r"(a0), "r"(a1), "r"(a2), "r"(a3), "r"(b0), "r"(b1));
}

// ---------------------------------------------------------------------------
// Projection v7 (tensor cores, bf16 hi/lo split precision):
// C[row][g] = x[row] . W[g] + bias[g], via mma.m16n8k16 with W as the A
// operand (fragments constant in registers), x staged per 32-row tile as
// bf16 hi/lo in smem. C = Ah.Bh + Al.Bh + Ah.Bl (Al.Bl ~2^-16, dropped).
// 18 warps: warp w owns gates [16w, 16w+16). K = 100 padded to 112 (7 steps).
// ---------------------------------------------------------------------------
__global__ __launch_bounds__(PROJ_T, 1) void proj_kernel(
    const float* __restrict__ x,
    const float* __restrict__ w_ih_f, const float* __restrict__ b_ih_f,
    const float* __restrict__ w_ih_b, const float* __restrict__ b_ih_b)
{
    const int dir    = blockIdx.x & 1;
    const int chunk  = blockIdx.x >> 1;
    const int nchunk = gridDim.x >> 1;
    const long R = (long)T_LEN * B_SZ;
    const long rows_per = (R + nchunk - 1) / nchunk;
    const long r0 = (long)chunk * rows_per;
    const long r1 = (r0 + rows_per < R) ? (r0 + rows_per) : R;

    const float* w    = dir ? w_ih_b : w_ih_f;
    const float* bias = dir ? b_ih_b : b_ih_f;
    float* xp = g_xproj + (size_t)dir * T_LEN * B_SZ * G3;

    const int t     = threadIdx.x;
    const int warp  = t >> 5;
    const int lane  = t & 31;
    const int gid   = lane >> 2;   // groupID 0..7
    const int tig   = lane & 3;    // thread-in-group 0..3
    const int gbase = warp * 16;

    // A fragments (weights), hi and lo: 7 k-steps x 4 regs each.
    // reg0: (g, 2t..+1), reg1: (g+8, 2t..), reg2: (g, 2t+8..), reg3: (g+8, 2t+8..)
    u32 ah[7][4], al[7][4];
    {
        const int glo = gbase + gid, ghi = glo + 8;
        #pragma unroll
        for (int kk = 0; kk < 7; kk++) {
            const int kb = 16 * kk + 2 * tig;
            #pragma unroll
            for (int rg = 0; rg < 4; rg++) {
                const int gg = (rg & 1) ? ghi : glo;
                const int k0 = kb + ((rg & 2) ? 8 : 0);
                float w0 = (k0     < I_SZ) ? w[gg * I_SZ + k0]     : 0.0f;
                float w1 = (k0 + 1 < I_SZ) ? w[gg * I_SZ + k0 + 1] : 0.0f;
                float h0, l0, h1, l1;
                bfsplit(w0, h0, l0);
                bfsplit(w1, h1, l1);
                ah[kk][rg] = bfpack(h0, h1);
                al[kk][rg] = bfpack(l0, l1);
            }
        }
    }
    const float bs_lo = bias[gbase + gid];
    const float bs_hi = bias[gbase + gid + 8];

    // smem: x tile as bf16 hi/lo, 32 rows x 120 halves (cols 100-119 stay 0)
    __shared__ unsigned short Xh[32][XROW], Xl[32][XROW];
    for (int i = t; i < 32 * XROW / 2; i += PROJ_T) {
        ((u32*)Xh)[i] = 0u;
        ((u32*)Xl)[i] = 0u;
    }
    __syncthreads();

    for (long row0 = r0; row0 < r1; row0 += 32) {
        // --- convert 32 rows fp32 -> bf16 hi/lo in smem ---
        for (int idx = t; idx < 32 * 25; idx += PROJ_T) {
            const int rr = idx / 25;
            const int c4 = idx % 25;
            if (row0 + rr < r1) {
                float4 v = ((const float4*)(x + (row0 + rr) * I_SZ))[c4];
                float h0, l0, h1, l1, h2, l2, h3, l3;
                bfsplit(v.x, h0, l0);
                bfsplit(v.y, h1, l1);
                bfsplit(v.z, h2, l2);
                bfsplit(v.w, h3, l3);
                *(u32*)&Xh[rr][c4 * 4]     = bfpack(h0, h1);
                *(u32*)&Xh[rr][c4 * 4 + 2] = bfpack(h2, h3);
                *(u32*)&Xl[rr][c4 * 4]     = bfpack(l0, l1);
                *(u32*)&Xl[rr][c4 * 4 + 2] = bfpack(l2, l3);
            }
        }
        __syncthreads();

        // --- mma: 4 groups of 8 rows ---
        #pragma unroll
        for (int grp = 0; grp < 4; grp++) {
            float c0 = bs_lo, c1 = bs_lo, c2 = bs_hi, c3 = bs_hi;
            const int rr = grp * 8 + gid;   // B column n = groupID

            u32 bh[7][2];
            #pragma unroll
            for (int kk = 0; kk < 7; kk++) {
                bh[kk][0] = *(const u32*)&Xh[rr][16 * kk + 2 * tig];
                bh[kk][1] = *(const u32*)&Xh[rr][16 * kk + 2 * tig + 8];
            }
            #pragma unroll
            for (int kk = 0; kk < 7; kk++)
                mma_bf16(c0, c1, c2, c3, ah[kk][0], ah[kk][1], ah[kk][2], ah[kk][3],
                         bh[kk][0], bh[kk][1]);
            #pragma unroll
            for (int kk = 0; kk < 7; kk++)
                mma_bf16(c0, c1, c2, c3, al[kk][0], al[kk][1], al[kk][2], al[kk][3],
                         bh[kk][0], bh[kk][1]);

            u32 bl[7][2];
            #pragma unroll
            for (int kk = 0; kk < 7; kk++) {
                bl[kk][0] = *(const u32*)&Xl[rr][16 * kk + 2 * tig];
                bl[kk][1] = *(const u32*)&Xl[rr][16 * kk + 2 * tig + 8];
            }
            #pragma unroll
            for (int kk = 0; kk < 7; kk++)
                mma_bf16(c0, c1, c2, c3, ah[kk][0], ah[kk][1], ah[kk][2], ah[kk][3],
                         bl[kk][0], bl[kk][1]);

            // C: c0=(g,2t) c1=(g,2t+1) c2=(g+8,2t) c3=(g+8,2t+1); n = x-row
            const long ra = row0 + grp * 8 + 2 * tig;
            const long rb = ra + 1;
            if (ra < r1) {
                xp[ra * G3 + gbase + gid]     = c0;
                xp[ra * G3 + gbase + gid + 8] = c2;
            }
            if (rb < r1) {
                xp[rb * G3 + gbase + gid]     = c1;
                xp[rb * G3 + gbase + gid + 8] = c3;
            }
        }
        __syncthreads();   // smem reuse next tile
    }
}

// ---------------------------------------------------------------------------
// Scan (R10 winner, unchanged): 384 threads, thread = (j, q), owns gate rows
// j, j+96, j+192; duty lanes compute gates in registers; h double-buffered
// in smem; ONE __syncthreads per step.
// ---------------------------------------------------------------------------
__global__ __launch_bounds__(SCAN_T, 1) void scan_kernel(
    const float* __restrict__ w_hh_f, const float* __restrict__ b_hh_f,
    const float* __restrict__ w_hh_b, const float* __restrict__ b_hh_b,
    float* __restrict__ out)
{
    const int dir = blockIdx.y;
    const int b0  = blockIdx.x * BCH;
    const float* w    = dir ? w_hh_b : w_hh_f;
    const float* bias = dir ? b_hh_b : b_hh_f;
    const float* xp = g_xproj + (size_t)dir * T_LEN * B_SZ * G3;

    const int t    = threadIdx.x;
    const int lane = t & 31;
    const int q    = lane >> 3;
    const int j    = (t >> 5) * 8 + (lane & 7);   // 0..95

    u64 wr[3][12];
    #pragma unroll
    for (int r = 0; r < 3; r++) {
        const u64* p = (const u64*)(w + (j + 96 * r) * H_SZ + 24 * q);
        #pragma unroll
        for (int k = 0; k < 12; k++) wr[r][k] = p[k];
    }
    float bg[3];
    #pragma unroll
    for (int r = 0; r < 3; r++) bg[r] = q ? 0.0f : bias[j + 96 * r];

    __shared__ __align__(16) float h_s[2][BCH][HPAD];
    for (int idx = t; idx < 2 * BCH * HPAD; idx += SCAN_T) ((float*)h_s)[idx] = 0.0f;

    const int bd0 = q;
    const int bd1 = q + 4;
    const bool d1v = (bd1 < BCH);
    int row0 = b0 + bd0; if (row0 > B_SZ - 1) row0 = B_SZ - 1;
    int row1 = b0 + (d1v ? bd1 : 0); if (row1 > B_SZ - 1) row1 = B_SZ - 1;
    const bool w0v = (b0 + bd0 < B_SZ);
    const bool w1v = d1v && (b0 + bd1 < B_SZ);

    float hold0 = 0.0f, hold1 = 0.0f;

    float xq0[3], xq1[3];
    {
        const int t0 = dir ? (T_LEN - 1) : 0;
        const float* p0 = xp + ((size_t)t0 * B_SZ + row0) * G3 + j;
        const float* p1 = xp + ((size_t)t0 * B_SZ + row1) * G3 + j;
        #pragma unroll
        for (int r = 0; r < 3; r++) {
            xq0[r] = p0[96 * r];
            xq1[r] = d1v ? p1[96 * r] : 0.0f;
        }
    }
    __syncthreads();

    int p = 0;
    for (int it = 0; it < T_LEN; it++) {
        const int tc = dir ? (T_LEN - 1 - it) : it;

        float xn0[3], xn1[3];
        #pragma unroll
        for (int r = 0; r < 3; r++) { xn0[r] = 0.0f; xn1[r] = 0.0f; }
        if (it + 1 < T_LEN) {
            const int tn = dir ? (T_LEN - 2 - it) : (it + 1);
            const float* p0 = xp + ((size_t)tn * B_SZ + row0) * G3 + j;
            const float* p1 = xp + ((size_t)tn * B_SZ + row1) * G3 + j;
            #pragma unroll
            for (int r = 0; r < 3; r++) {
                xn0[r] = p0[96 * r];
                xn1[r] = d1v ? p1[96 * r] : 0.0f;
            }
        }

        u64 acc[3][BCH];
        #pragma unroll
        for (int r = 0; r < 3; r++)
            #pragma unroll
            for (int b = 0; b < BCH; b++) acc[r][b] = pack2(bg[r], 0.0f);

        const ulonglong2* h2 = (const ulonglong2*)h_s[p] + q * 6;
        #pragma unroll
        for (int kk = 0; kk < 6; kk++) {
            #pragma unroll
            for (int b = 0; b < BCH; b++) {
                ulonglong2 hv = h2[b * (HPAD / 4) + kk];
                #pragma unroll
                for (int r = 0; r < 3; r++) {
                    acc[r][b] = ffma2(hv.x, wr[r][2 * kk],     acc[r][b]);
                    acc[r][b] = ffma2(hv.y, wr[r][2 * kk + 1], acc[r][b]);
                }
            }
        }

        float v0d[3], v1d[3];
        #pragma unroll
        for (int r = 0; r < 3; r++) {
            #pragma unroll
            for (int b = 0; b < BCH; b++) {
                const float vv = qreduce(hsum2(acc[r][b]));
                if (b == bd0) v0d[r] = vv;
                if (d1v && b == bd1) v1d[r] = vv;
            }
        }

        {
            const float rg = fast_sigmoid(v0d[0] + xq0[0]);
            const float zg = fast_sigmoid(v0d[1] + xq0[1]);
            const float ng = fast_tanh(fmaf(rg, v0d[2], xq0[2]));
            const float hn = fmaf(zg, hold0 - ng, ng);
            hold0 = hn;
            h_s[p ^ 1][bd0][j] = hn;
            if (w0v)
                out[((size_t)tc * B_SZ + (b0 + bd0)) * (2 * H_SZ) + dir * H_SZ + j] = hn;
        }
        if (d1v) {
            const float rg = fast_sigmoid(v1d[0] + xq1[0]);
            const float zg = fast_sigmoid(v1d[1] + xq1[1]);
            const float ng = fast_tanh(fmaf(rg, v1d[2], xq1[2]));
            const float hn = fmaf(zg, hold1 - ng, ng);
            hold1 = hn;
            h_s[p ^ 1][bd1][j] = hn;
            if (w1v)
                out[((size_t)tc * B_SZ + (b0 + bd1)) * (2 * H_SZ) + dir * H_SZ + j] = hn;
        }

        #pragma unroll
        for (int r = 0; r < 3; r++) { xq0[r] = xn0[r]; xq1[r] = xn1[r]; }

        __syncthreads();
        p ^= 1;
    }
}

extern "C" void kernel_launch(void* const* d_in, const int* in_sizes, int n_in,
                              void* d_out, int out_size) {
    const float* x    = (const float*)d_in[0];
    const float* wihf = (const float*)d_in[1];
    const float* whhf = (const float*)d_in[2];
    const float* bihf = (const float*)d_in[3];
    const float* bhhf = (const float*)d_in[4];
    const float* wihb = (const float*)d_in[5];
    const float* whhb = (const float*)d_in[6];
    const float* bihb = (const float*)d_in[7];
    const float* bhhb = (const float*)d_in[8];
    float* out = (float*)d_out;

    proj_kernel<<<296, PROJ_T>>>(x, wihf, bihf, wihb, bihb);
    dim3 sg(NCHUNK, 2);
    scan_kernel<<<sg, SCAN_T>>>(whhf, bhhf, whhb, bhhb, out);
}

// round 14
// speedup vs baseline: 2.3300x; 1.2482x over previous
#include <cuda_runtime.h>
#include <cuda_bf16.h>

#define T_LEN 512
#define B_SZ  512
#define I_SZ  100
#define H_SZ  96
#define G3    288   // 3*H
#define PROJ_T 576   // 18 warps = 18 m16 gate-slices
#define SCAN_T 576   // 18 warps (MMA) / 384 gate threads
#define SBCH  8      // batch rows per scan block (64 chunks x 2 dirs = 128 blocks)
#define SNCHUNK 64
#define HPROW 296    // hp row stride in floats (conflict-tuned)
#define FROW  36     // Fh/Fl row stride in u64 (≡4 mod 16 -> conflict-free LDS.64)
#define XROW  120    // proj smem x row stride in bf16 halves

typedef unsigned int u32;
typedef unsigned long long u64;

// Scratch: input projections for both directions: [2][T][B][3H] fp32
static __device__ float g_xproj[2ull * T_LEN * B_SZ * G3];

__device__ __forceinline__ float fast_sigmoid(float x) {
    float e, r;
    asm("ex2.approx.f32 %0, %1;" : "=f"(e) : "f"(-1.4426950408889634f * x));
    asm("rcp.approx.f32 %0, %1;" : "=f"(r) : "f"(1.0f + e));
    return r;
}
__device__ __forceinline__ float fast_tanh(float x) {
    float e, r;
    asm("ex2.approx.f32 %0, %1;" : "=f"(e) : "f"(-2.8853900817779268f * x));
    asm("rcp.approx.f32 %0, %1;" : "=f"(r) : "f"(1.0f + e));
    return 2.0f * r - 1.0f;
}

// ---- bf16 helpers ----
__device__ __forceinline__ u32 bfpack(float a, float b) {
    // low 16 bits = a (even k), high = b (odd k)
    unsigned short sa = __bfloat16_as_ushort(__float2bfloat16(a));
    unsigned short sb = __bfloat16_as_ushort(__float2bfloat16(b));
    return (u32)sa | ((u32)sb << 16);
}
__device__ __forceinline__ void bfsplit(float v, float& hi, float& lo) {
    __nv_bfloat16 h = __float2bfloat16(v);
    hi = __bfloat162float(h);
    lo = v - hi;
}

__device__ __forceinline__ void mma_bf16(
    float& c0, float& c1, float& c2, float& c3,
    u32 a0, u32 a1, u32 a2, u32 a3, u32 b0, u32 b1)
{
    asm("mma.sync.aligned.m16n8k16.row.col.f32.bf16.bf16.f32 "
        "{%0,%1,%2,%3}, {%4,%5,%6,%7}, {%8,%9}, {%0,%1,%2,%3};"
        : "+f"(c0), "+f"(c1), "+f"(c2), "+f"(c3)
        : "r"(a0), "r"(a1), "r"(a2), "r"(a3), "r"(b0), "r"(b1));
}

// ---------------------------------------------------------------------------
// Projection (R13 winner, unchanged): tensor cores, bf16 hi/lo split.
// ---------------------------------------------------------------------------
__global__ __launch_bounds__(PROJ_T, 1) void proj_kernel(
    const float* __restrict__ x,
    const float* __restrict__ w_ih_f, const float* __restrict__ b_ih_f,
    const float* __restrict__ w_ih_b, const float* __restrict__ b_ih_b)
{
    const int dir    = blockIdx.x & 1;
    const int chunk  = blockIdx.x >> 1;
    const int nchunk = gridDim.x >> 1;
    const long R = (long)T_LEN * B_SZ;
    const long rows_per = (R + nchunk - 1) / nchunk;
    const long r0 = (long)chunk * rows_per;
    const long r1 = (r0 + rows_per < R) ? (r0 + rows_per) : R;

    const float* w    = dir ? w_ih_b : w_ih_f;
    const float* bias = dir ? b_ih_b : b_ih_f;
    float* xp = g_xproj + (size_t)dir * T_LEN * B_SZ * G3;

    const int t     = threadIdx.x;
    const int warp  = t >> 5;
    const int lane  = t & 31;
    const int gid   = lane >> 2;
    const int tig   = lane & 3;
    const int gbase = warp * 16;

    u32 ah[7][4], al[7][4];
    {
        const int glo = gbase + gid, ghi = glo + 8;
        #pragma unroll
        for (int kk = 0; kk < 7; kk++) {
            const int kb = 16 * kk + 2 * tig;
            #pragma unroll
            for (int rg = 0; rg < 4; rg++) {
                const int gg = (rg & 1) ? ghi : glo;
                const int k0 = kb + ((rg & 2) ? 8 : 0);
                float w0 = (k0     < I_SZ) ? w[gg * I_SZ + k0]     : 0.0f;
                float w1 = (k0 + 1 < I_SZ) ? w[gg * I_SZ + k0 + 1] : 0.0f;
                float h0, l0, h1, l1;
                bfsplit(w0, h0, l0);
                bfsplit(w1, h1, l1);
                ah[kk][rg] = bfpack(h0, h1);
                al[kk][rg] = bfpack(l0, l1);
            }
        }
    }
    const float bs_lo = bias[gbase + gid];
    const float bs_hi = bias[gbase + gid + 8];

    __shared__ unsigned short Xh[32][XROW], Xl[32][XROW];
    for (int i = t; i < 32 * XROW / 2; i += PROJ_T) {
        ((u32*)Xh)[i] = 0u;
        ((u32*)Xl)[i] = 0u;
    }
    __syncthreads();

    for (long row0 = r0; row0 < r1; row0 += 32) {
        for (int idx = t; idx < 32 * 25; idx += PROJ_T) {
            const int rr = idx / 25;
            const int c4 = idx % 25;
            if (row0 + rr < r1) {
                float4 v = ((const float4*)(x + (row0 + rr) * I_SZ))[c4];
                float h0, l0, h1, l1, h2, l2, h3, l3;
                bfsplit(v.x, h0, l0);
                bfsplit(v.y, h1, l1);
                bfsplit(v.z, h2, l2);
                bfsplit(v.w, h3, l3);
                *(u32*)&Xh[rr][c4 * 4]     = bfpack(h0, h1);
                *(u32*)&Xh[rr][c4 * 4 + 2] = bfpack(h2, h3);
                *(u32*)&Xl[rr][c4 * 4]     = bfpack(l0, l1);
                *(u32*)&Xl[rr][c4 * 4 + 2] = bfpack(l2, l3);
            }
        }
        __syncthreads();

        #pragma unroll
        for (int grp = 0; grp < 4; grp++) {
            float c0 = bs_lo, c1 = bs_lo, c2 = bs_hi, c3 = bs_hi;
            const int rr = grp * 8 + gid;

            u32 bh[7][2];
            #pragma unroll
            for (int kk = 0; kk < 7; kk++) {
                bh[kk][0] = *(const u32*)&Xh[rr][16 * kk + 2 * tig];
                bh[kk][1] = *(const u32*)&Xh[rr][16 * kk + 2 * tig + 8];
            }
            #pragma unroll
            for (int kk = 0; kk < 7; kk++)
                mma_bf16(c0, c1, c2, c3, ah[kk][0], ah[kk][1], ah[kk][2], ah[kk][3],
                         bh[kk][0], bh[kk][1]);
            #pragma unroll
            for (int kk = 0; kk < 7; kk++)
                mma_bf16(c0, c1, c2, c3, al[kk][0], al[kk][1], al[kk][2], al[kk][3],
                         bh[kk][0], bh[kk][1]);

            u32 bl[7][2];
            #pragma unroll
            for (int kk = 0; kk < 7; kk++) {
                bl[kk][0] = *(const u32*)&Xl[rr][16 * kk + 2 * tig];
                bl[kk][1] = *(const u32*)&Xl[rr][16 * kk + 2 * tig + 8];
            }
            #pragma unroll
            for (int kk = 0; kk < 7; kk++)
                mma_bf16(c0, c1, c2, c3, ah[kk][0], ah[kk][1], ah[kk][2], ah[kk][3],
                         bl[kk][0], bl[kk][1]);

            const long ra = row0 + grp * 8 + 2 * tig;
            const long rb = ra + 1;
            if (ra < r1) {
                xp[ra * G3 + gbase + gid]     = c0;
                xp[ra * G3 + gbase + gid + 8] = c2;
            }
            if (rb < r1) {
                xp[rb * G3 + gbase + gid]     = c1;
                xp[rb * G3 + gbase + gid + 8] = c3;
            }
        }
        __syncthreads();
    }
}

// ---------------------------------------------------------------------------
// Scan v2 (tensor cores): block owns 8 batch rows of one direction.
// 18 warps; warp w = m16 gate-slice [16w,16w+16). A = W_hh hi/lo fragments
// (constant registers). B = h as bf16 hi/lo in fragment layout Fh/Fl[b][36]
// u64 (unit (kk,tig): low u32 = k 16kk+2tig..+1, high = +8..+9 of batch b).
// Phase 1: 18 MMAs -> hp[b][g] staged to smem. Phase 2: 384 gate threads
// (b, j-pair) read hp as float2, compute gates, write out + next B-frags.
// 2 barriers per step.
// ---------------------------------------------------------------------------
__global__ __launch_bounds__(SCAN_T, 1) void scan_kernel(
    const float* __restrict__ w_hh_f, const float* __restrict__ b_hh_f,
    const float* __restrict__ w_hh_b, const float* __restrict__ b_hh_b,
    float* __restrict__ out)
{
    const int dir = blockIdx.y;
    const int b0  = blockIdx.x * SBCH;
    const float* w    = dir ? w_hh_b : w_hh_f;
    const float* bias = dir ? b_hh_b : b_hh_f;
    const float* xp = g_xproj + (size_t)dir * T_LEN * B_SZ * G3;

    const int t    = threadIdx.x;
    const int warp = t >> 5;
    const int lane = t & 31;
    const int gid  = lane >> 2;
    const int tig  = lane & 3;
    const int glo  = warp * 16 + gid;
    const int ghi  = glo + 8;

    // A fragments (W_hh), hi/lo: 6 k-steps x 4 regs (same layout as proj)
    u32 ah[6][4], al[6][4];
    #pragma unroll
    for (int kk = 0; kk < 6; kk++) {
        const int kb = 16 * kk + 2 * tig;
        #pragma unroll
        for (int rg = 0; rg < 4; rg++) {
            const int gg = (rg & 1) ? ghi : glo;
            const int k0 = kb + ((rg & 2) ? 8 : 0);
            float w0 = w[gg * H_SZ + k0];
            float w1 = w[gg * H_SZ + k0 + 1];
            float h0, l0, h1, l1;
            bfsplit(w0, h0, l0);
            bfsplit(w1, h1, l1);
            ah[kk][rg] = bfpack(h0, h1);
            al[kk][rg] = bfpack(l0, l1);
        }
    }
    const float bs_lo = bias[glo];
    const float bs_hi = bias[ghi];

    __shared__ float hp[SBCH][HPROW];        // hidden-proj staging
    __shared__ u64 Fh[SBCH][FROW], Fl[SBCH][FROW];   // B-fragments (bf16 hi/lo)

    // zero B-frags (h0 = 0)
    for (int i = t; i < SBCH * FROW; i += SCAN_T) {
        ((u64*)Fh)[i] = 0ull;
        ((u64*)Fl)[i] = 0ull;
    }

    // gate role: t < 384 -> (batch gb, j-pair jp)
    const bool gate_on = t < SBCH * 48;
    const int gb = t / 48;
    const int jp = t % 48;
    const int funit = 4 * (jp >> 3) + (jp & 3);   // u64 unit in Fh/Fl row
    const int fsel  = (jp & 7) >> 2;              // low/high u32 of that unit
    float hold0 = 0.0f, hold1 = 0.0f;

    float2 xqr, xqz, xqn;
    if (gate_on) {
        const int t0 = dir ? (T_LEN - 1) : 0;
        const float* base = xp + ((size_t)t0 * B_SZ + b0 + gb) * G3 + 2 * jp;
        xqr = *(const float2*)(base);
        xqz = *(const float2*)(base + 96);
        xqn = *(const float2*)(base + 192);
    }
    __syncthreads();

    for (int it = 0; it < T_LEN; it++) {
        const int tc = dir ? (T_LEN - 1 - it) : it;

        // ---- Phase 1: MMA (hp = W_hh . h + b_hh) ----
        float c0 = bs_lo, c1 = bs_lo, c2 = bs_hi, c3 = bs_hi;
        {
            u32 br0[6], br1[6];
            #pragma unroll
            for (int kk = 0; kk < 6; kk++) {
                u64 v = Fh[gid][4 * kk + tig];
                br0[kk] = (u32)v;
                br1[kk] = (u32)(v >> 32);
            }
            #pragma unroll
            for (int kk = 0; kk < 6; kk++)
                mma_bf16(c0, c1, c2, c3, ah[kk][0], ah[kk][1], ah[kk][2], ah[kk][3],
                         br0[kk], br1[kk]);
            #pragma unroll
            for (int kk = 0; kk < 6; kk++)
                mma_bf16(c0, c1, c2, c3, al[kk][0], al[kk][1], al[kk][2], al[kk][3],
                         br0[kk], br1[kk]);
            #pragma unroll
            for (int kk = 0; kk < 6; kk++) {
                u64 v = Fl[gid][4 * kk + tig];
                br0[kk] = (u32)v;
                br1[kk] = (u32)(v >> 32);
            }
            #pragma unroll
            for (int kk = 0; kk < 6; kk++)
                mma_bf16(c0, c1, c2, c3, ah[kk][0], ah[kk][1], ah[kk][2], ah[kk][3],
                         br0[kk], br1[kk]);
        }
        // C: c0=(glo, b=2tig) c1=(glo, 2tig+1) c2=(ghi, 2tig) c3=(ghi, 2tig+1)
        hp[2 * tig][glo]     = c0;
        hp[2 * tig + 1][glo] = c1;
        hp[2 * tig][ghi]     = c2;
        hp[2 * tig + 1][ghi] = c3;
        __syncthreads();

        // ---- Phase 2: gates (384 threads) ----
        if (gate_on) {
            const float2 hr = *(const float2*)&hp[gb][2 * jp];
            const float2 hz = *(const float2*)&hp[gb][96 + 2 * jp];
            const float2 hn = *(const float2*)&hp[gb][192 + 2 * jp];

            const float r0 = fast_sigmoid(hr.x + xqr.x);
            const float r1 = fast_sigmoid(hr.y + xqr.y);
            const float z0 = fast_sigmoid(hz.x + xqz.x);
            const float z1 = fast_sigmoid(hz.y + xqz.y);
            const float n0 = fast_tanh(fmaf(r0, hn.x, xqn.x));
            const float n1 = fast_tanh(fmaf(r1, hn.y, xqn.y));
            const float h0 = fmaf(z0, hold0 - n0, n0);
            const float h1 = fmaf(z1, hold1 - n1, n1);
            hold0 = h0;
            hold1 = h1;

            // output
            float2 o2 = make_float2(h0, h1);
            *(float2*)&out[((size_t)tc * B_SZ + b0 + gb) * (2 * H_SZ)
                           + dir * H_SZ + 2 * jp] = o2;

            // pack next step's B-fragments (bf16 hi/lo)
            float hi0, lo0, hi1, lo1;
            bfsplit(h0, hi0, lo0);
            bfsplit(h1, hi1, lo1);
            ((u32*)&Fh[gb][funit])[fsel] = bfpack(hi0, hi1);
            ((u32*)&Fl[gb][funit])[fsel] = bfpack(lo0, lo1);

            // prefetch next step's xq
            if (it + 1 < T_LEN) {
                const int tn = dir ? (T_LEN - 2 - it) : (it + 1);
                const float* base = xp + ((size_t)tn * B_SZ + b0 + gb) * G3 + 2 * jp;
                xqr = *(const float2*)(base);
                xqz = *(const float2*)(base + 96);
                xqn = *(const float2*)(base + 192);
            }
        }
        __syncthreads();
    }
}

extern "C" void kernel_launch(void* const* d_in, const int* in_sizes, int n_in,
                              void* d_out, int out_size) {
    const float* x    = (const float*)d_in[0];
    const float* wihf = (const float*)d_in[1];
    const float* whhf = (const float*)d_in[2];
    const float* bihf = (const float*)d_in[3];
    const float* bhhf = (const float*)d_in[4];
    const float* wihb = (const float*)d_in[5];
    const float* whhb = (const float*)d_in[6];
    const float* bihb = (const float*)d_in[7];
    const float* bhhb = (const float*)d_in[8];
    float* out = (float*)d_out;

    proj_kernel<<<296, PROJ_T>>>(x, wihf, bihf, wihb, bihb);
    dim3 sg(SNCHUNK, 2);
    scan_kernel<<<sg, SCAN_T>>>(whhf, bhhf, whhb, bhhb, out);
}

// round 16
// speedup vs baseline: 2.3768x; 1.0201x over previous
#include <cuda_runtime.h>
#include <cuda_bf16.h>

#define T_LEN 512
#define B_SZ  512
#define I_SZ  100
#define H_SZ  96
#define G3    288   // 3*H
#define PROJ_T 576   // 18 warps = 18 m16 gate-slices
#define SCAN_T 576   // 18 warps (MMA) / 384 gate threads
#define SBCH  8      // batch rows per scan block (64 chunks x 2 dirs = 128 blocks)
#define SNCHUNK 64
#define HPROW 296    // hp row stride in floats (conflict-tuned)
#define FROW  36     // Fh/Fl row stride in u64 (≡4 mod 16 -> conflict-free LDS.64)
#define XROW  120    // proj smem x row stride in bf16 halves

typedef unsigned int u32;
typedef unsigned long long u64;

// Scratch: input projections for both directions: [2][T][B][3H] fp32
static __device__ float g_xproj[2ull * T_LEN * B_SZ * G3];

__device__ __forceinline__ float fast_sigmoid(float x) {
    float e, r;
    asm("ex2.approx.f32 %0, %1;" : "=f"(e) : "f"(-1.4426950408889634f * x));
    asm("rcp.approx.f32 %0, %1;" : "=f"(r) : "f"(1.0f + e));
    return r;
}
__device__ __forceinline__ float fast_tanh(float x) {
    float e, r;
    asm("ex2.approx.f32 %0, %1;" : "=f"(e) : "f"(-2.8853900817779268f * x));
    asm("rcp.approx.f32 %0, %1;" : "=f"(r) : "f"(1.0f + e));
    return 2.0f * r - 1.0f;
}

// ---- bf16 helpers ----
__device__ __forceinline__ u32 bfpack(float a, float b) {
    unsigned short sa = __bfloat16_as_ushort(__float2bfloat16(a));
    unsigned short sb = __bfloat16_as_ushort(__float2bfloat16(b));
    return (u32)sa | ((u32)sb << 16);
}
__device__ __forceinline__ void bfsplit(float v, float& hi, float& lo) {
    __nv_bfloat16 h = __float2bfloat16(v);
    hi = __bfloat162float(h);
    lo = v - hi;
}

__device__ __forceinline__ void mma_bf16(
    float& c0, float& c1, float& c2, float& c3,
    u32 a0, u32 a1, u32 a2, u32 a3, u32 b0, u32 b1)
{
    asm("mma.sync.aligned.m16n8k16.row.col.f32.bf16.bf16.f32 "
        "{%0,%1,%2,%3}, {%4,%5,%6,%7}, {%8,%9}, {%0,%1,%2,%3};"
        : "+f"(c0), "+f"(c1), "+f"(c2), "+f"(c3)
        : "r"(a0), "r"(a1), "r"(a2), "r"(a3), "r"(b0), "r"(b1));
}

// ---------------------------------------------------------------------------
// Projection (tensor cores, bf16 hi/lo split; 3 independent accumulator
// quads per row-group to break the HMMA dependency chain).
// ---------------------------------------------------------------------------
__global__ __launch_bounds__(PROJ_T, 1) void proj_kernel(
    const float* __restrict__ x,
    const float* __restrict__ w_ih_f, const float* __restrict__ b_ih_f,
    const float* __restrict__ w_ih_b, const float* __restrict__ b_ih_b)
{
    const int dir    = blockIdx.x & 1;
    const int chunk  = blockIdx.x >> 1;
    const int nchunk = gridDim.x >> 1;
    const long R = (long)T_LEN * B_SZ;
    const long rows_per = (R + nchunk - 1) / nchunk;
    const long r0 = (long)chunk * rows_per;
    const long r1 = (r0 + rows_per < R) ? (r0 + rows_per) : R;

    const float* w    = dir ? w_ih_b : w_ih_f;
    const float* bias = dir ? b_ih_b : b_ih_f;
    float* xp = g_xproj + (size_t)dir * T_LEN * B_SZ * G3;

    const int t     = threadIdx.x;
    const int warp  = t >> 5;
    const int lane  = t & 31;
    const int gid   = lane >> 2;
    const int tig   = lane & 3;
    const int gbase = warp * 16;

    u32 ah[7][4], al[7][4];
    {
        const int glo = gbase + gid, ghi = glo + 8;
        #pragma unroll
        for (int kk = 0; kk < 7; kk++) {
            const int kb = 16 * kk + 2 * tig;
            #pragma unroll
            for (int rg = 0; rg < 4; rg++) {
                const int gg = (rg & 1) ? ghi : glo;
                const int k0 = kb + ((rg & 2) ? 8 : 0);
                float w0 = (k0     < I_SZ) ? w[gg * I_SZ + k0]     : 0.0f;
                float w1 = (k0 + 1 < I_SZ) ? w[gg * I_SZ + k0 + 1] : 0.0f;
                float h0, l0, h1, l1;
                bfsplit(w0, h0, l0);
                bfsplit(w1, h1, l1);
                ah[kk][rg] = bfpack(h0, h1);
                al[kk][rg] = bfpack(l0, l1);
            }
        }
    }
    const float bs_lo = bias[gbase + gid];
    const float bs_hi = bias[gbase + gid + 8];

    __shared__ unsigned short Xh[32][XROW], Xl[32][XROW];
    for (int i = t; i < 32 * XROW / 2; i += PROJ_T) {
        ((u32*)Xh)[i] = 0u;
        ((u32*)Xl)[i] = 0u;
    }
    __syncthreads();

    for (long row0 = r0; row0 < r1; row0 += 32) {
        for (int idx = t; idx < 32 * 25; idx += PROJ_T) {
            const int rr = idx / 25;
            const int c4 = idx % 25;
            if (row0 + rr < r1) {
                float4 v = ((const float4*)(x + (row0 + rr) * I_SZ))[c4];
                float h0, l0, h1, l1, h2, l2, h3, l3;
                bfsplit(v.x, h0, l0);
                bfsplit(v.y, h1, l1);
                bfsplit(v.z, h2, l2);
                bfsplit(v.w, h3, l3);
                *(u32*)&Xh[rr][c4 * 4]     = bfpack(h0, h1);
                *(u32*)&Xh[rr][c4 * 4 + 2] = bfpack(h2, h3);
                *(u32*)&Xl[rr][c4 * 4]     = bfpack(l0, l1);
                *(u32*)&Xl[rr][c4 * 4 + 2] = bfpack(l2, l3);
            }
        }
        __syncthreads();

        #pragma unroll
        for (int grp = 0; grp < 4; grp++) {
            // 3 independent accumulator quads (chain = 7 HMMA, not 21)
            float p0 = bs_lo, p1 = bs_lo, p2 = bs_hi, p3 = bs_hi;
            float q0 = 0.f, q1 = 0.f, q2 = 0.f, q3 = 0.f;
            float s0 = 0.f, s1 = 0.f, s2 = 0.f, s3 = 0.f;
            const int rr = grp * 8 + gid;

            u32 bh[7][2], bl[7][2];
            #pragma unroll
            for (int kk = 0; kk < 7; kk++) {
                bh[kk][0] = *(const u32*)&Xh[rr][16 * kk + 2 * tig];
                bh[kk][1] = *(const u32*)&Xh[rr][16 * kk + 2 * tig + 8];
                bl[kk][0] = *(const u32*)&Xl[rr][16 * kk + 2 * tig];
                bl[kk][1] = *(const u32*)&Xl[rr][16 * kk + 2 * tig + 8];
            }
            #pragma unroll
            for (int kk = 0; kk < 7; kk++) {
                mma_bf16(p0, p1, p2, p3, ah[kk][0], ah[kk][1], ah[kk][2], ah[kk][3],
                         bh[kk][0], bh[kk][1]);
                mma_bf16(q0, q1, q2, q3, al[kk][0], al[kk][1], al[kk][2], al[kk][3],
                         bh[kk][0], bh[kk][1]);
                mma_bf16(s0, s1, s2, s3, ah[kk][0], ah[kk][1], ah[kk][2], ah[kk][3],
                         bl[kk][0], bl[kk][1]);
            }
            const float c0 = p0 + q0 + s0;
            const float c1 = p1 + q1 + s1;
            const float c2 = p2 + q2 + s2;
            const float c3 = p3 + q3 + s3;

            const long ra = row0 + grp * 8 + 2 * tig;
            const long rb = ra + 1;
            if (ra < r1) {
                xp[ra * G3 + gbase + gid]     = c0;
                xp[ra * G3 + gbase + gid + 8] = c2;
            }
            if (rb < r1) {
                xp[rb * G3 + gbase + gid]     = c1;
                xp[rb * G3 + gbase + gid + 8] = c3;
            }
        }
        __syncthreads();
    }
}

// ---------------------------------------------------------------------------
// Scan v3 (tensor cores, chain-broken): as R14 but the 18 HMMAs are split
// into 3 independent 6-deep accumulator chains summed at the end, and the
// Fl fragment loads issue together with the Fh loads.
// ---------------------------------------------------------------------------
__global__ __launch_bounds__(SCAN_T, 1) void scan_kernel(
    const float* __restrict__ w_hh_f, const float* __restrict__ b_hh_f,
    const float* __restrict__ w_hh_b, const float* __restrict__ b_hh_b,
    float* __restrict__ out)
{
    const int dir = blockIdx.y;
    const int b0  = blockIdx.x * SBCH;
    const float* w    = dir ? w_hh_b : w_hh_f;
    const float* bias = dir ? b_hh_b : b_hh_f;
    const float* xp = g_xproj + (size_t)dir * T_LEN * B_SZ * G3;

    const int t    = threadIdx.x;
    const int warp = t >> 5;
    const int lane = t & 31;
    const int gid  = lane >> 2;
    const int tig  = lane & 3;
    const int glo  = warp * 16 + gid;
    const int ghi  = glo + 8;

    u32 ah[6][4], al[6][4];
    #pragma unroll
    for (int kk = 0; kk < 6; kk++) {
        const int kb = 16 * kk + 2 * tig;
        #pragma unroll
        for (int rg = 0; rg < 4; rg++) {
            const int gg = (rg & 1) ? ghi : glo;
            const int k0 = kb + ((rg & 2) ? 8 : 0);
            float w0 = w[gg * H_SZ + k0];
            float w1 = w[gg * H_SZ + k0 + 1];
            float h0, l0, h1, l1;
            bfsplit(w0, h0, l0);
            bfsplit(w1, h1, l1);
            ah[kk][rg] = bfpack(h0, h1);
            al[kk][rg] = bfpack(l0, l1);
        }
    }
    const float bs_lo = bias[glo];
    const float bs_hi = bias[ghi];

    __shared__ float hp[SBCH][HPROW];
    __shared__ u64 Fh[SBCH][FROW], Fl[SBCH][FROW];

    for (int i = t; i < SBCH * FROW; i += SCAN_T) {
        ((u64*)Fh)[i] = 0ull;
        ((u64*)Fl)[i] = 0ull;
    }

    const bool gate_on = t < SBCH * 48;
    const int gb = t / 48;
    const int jp = t % 48;
    const int funit = 4 * (jp >> 3) + (jp & 3);
    const int fsel  = (jp & 7) >> 2;
    float hold0 = 0.0f, hold1 = 0.0f;

    float2 xqr, xqz, xqn;
    if (gate_on) {
        const int t0 = dir ? (T_LEN - 1) : 0;
        const float* base = xp + ((size_t)t0 * B_SZ + b0 + gb) * G3 + 2 * jp;
        xqr = *(const float2*)(base);
        xqz = *(const float2*)(base + 96);
        xqn = *(const float2*)(base + 192);
    }
    __syncthreads();

    for (int it = 0; it < T_LEN; it++) {
        const int tc = dir ? (T_LEN - 1 - it) : it;

        // ---- Phase 1: MMA, 3 independent accumulator chains ----
        float p0 = bs_lo, p1 = bs_lo, p2 = bs_hi, p3 = bs_hi;  // Ah.Bh + bias
        float q0 = 0.f, q1 = 0.f, q2 = 0.f, q3 = 0.f;          // Al.Bh
        float s0 = 0.f, s1 = 0.f, s2 = 0.f, s3 = 0.f;          // Ah.Bl
        {
            u32 bh0[6], bh1[6], bl0[6], bl1[6];
            #pragma unroll
            for (int kk = 0; kk < 6; kk++) {
                u64 vh = Fh[gid][4 * kk + tig];
                u64 vl = Fl[gid][4 * kk + tig];
                bh0[kk] = (u32)vh; bh1[kk] = (u32)(vh >> 32);
                bl0[kk] = (u32)vl; bl1[kk] = (u32)(vl >> 32);
            }
            #pragma unroll
            for (int kk = 0; kk < 6; kk++) {
                mma_bf16(p0, p1, p2, p3, ah[kk][0], ah[kk][1], ah[kk][2], ah[kk][3],
                         bh0[kk], bh1[kk]);
                mma_bf16(q0, q1, q2, q3, al[kk][0], al[kk][1], al[kk][2], al[kk][3],
                         bh0[kk], bh1[kk]);
                mma_bf16(s0, s1, s2, s3, ah[kk][0], ah[kk][1], ah[kk][2], ah[kk][3],
                         bl0[kk], bl1[kk]);
            }
        }
        const float c0 = p0 + q0 + s0;
        const float c1 = p1 + q1 + s1;
        const float c2 = p2 + q2 + s2;
        const float c3 = p3 + q3 + s3;

        hp[2 * tig][glo]     = c0;
        hp[2 * tig + 1][glo] = c1;
        hp[2 * tig][ghi]     = c2;
        hp[2 * tig + 1][ghi] = c3;
        __syncthreads();

        // ---- Phase 2: gates (384 threads) ----
        if (gate_on) {
            const float2 hr = *(const float2*)&hp[gb][2 * jp];
            const float2 hz = *(const float2*)&hp[gb][96 + 2 * jp];
            const float2 hn = *(const float2*)&hp[gb][192 + 2 * jp];

            const float r0 = fast_sigmoid(hr.x + xqr.x);
            const float r1 = fast_sigmoid(hr.y + xqr.y);
            const float z0 = fast_sigmoid(hz.x + xqz.x);
            const float z1 = fast_sigmoid(hz.y + xqz.y);
            const float n0 = fast_tanh(fmaf(r0, hn.x, xqn.x));
            const float n1 = fast_tanh(fmaf(r1, hn.y, xqn.y));
            const float h0 = fmaf(z0, hold0 - n0, n0);
            const float h1 = fmaf(z1, hold1 - n1, n1);
            hold0 = h0;
            hold1 = h1;

            float2 o2 = make_float2(h0, h1);
            *(float2*)&out[((size_t)tc * B_SZ + b0 + gb) * (2 * H_SZ)
                           + dir * H_SZ + 2 * jp] = o2;

            float hi0, lo0, hi1, lo1;
            bfsplit(h0, hi0, lo0);
            bfsplit(h1, hi1, lo1);
            ((u32*)&Fh[gb][funit])[fsel] = bfpack(hi0, hi1);
            ((u32*)&Fl[gb][funit])[fsel] = bfpack(lo0, lo1);

            if (it + 1 < T_LEN) {
                const int tn = dir ? (T_LEN - 2 - it) : (it + 1);
                const float* base = xp + ((size_t)tn * B_SZ + b0 + gb) * G3 + 2 * jp;
                xqr = *(const float2*)(base);
                xqz = *(const float2*)(base + 96);
                xqn = *(const float2*)(base + 192);
            }
        }
        __syncthreads();
    }
}

extern "C" void kernel_launch(void* const* d_in, const int* in_sizes, int n_in,
                              void* d_out, int out_size) {
    const float* x    = (const float*)d_in[0];
    const float* wihf = (const float*)d_in[1];
    const float* whhf = (const float*)d_in[2];
    const float* bihf = (const float*)d_in[3];
    const float* bhhf = (const float*)d_in[4];
    const float* wihb = (const float*)d_in[5];
    const float* whhb = (const float*)d_in[6];
    const float* bihb = (const float*)d_in[7];
    const float* bhhb = (const float*)d_in[8];
    float* out = (float*)d_out;

    proj_kernel<<<296, PROJ_T>>>(x, wihf, bihf, wihb, bihb);
    dim3 sg(SNCHUNK, 2);
    scan_kernel<<<sg, SCAN_T>>>(whhf, bhhf, whhb, bhhb, out);
}